// round 9
// baseline (speedup 1.0000x reference)
#include <cuda_runtime.h>
#include <math_constants.h>

// Problem constants (from reference setup_inputs)
static constexpr int NB  = 16;   // batch
static constexpr int CIN = 32;   // input channels
static constexpr int DIN = 16;
static constexpr int HIN = 32;
static constexpr int WIN = 32;
static constexpr int ODp = 5;    // pooled output dims
static constexpr int OHp = 10;
static constexpr int OWp = 10;

// Channel chunking: 4 phases of 8 channels; 9 packed accumulators in regs.
static constexpr int CHUNK = 8;
static constexpr int LWP   = 33;                       // padded x row (conflict-free)
static constexpr int XS_ELEMS = CHUNK * 5 * 5 * LWP;   // 6600
static constexpr int PM_ELEMS = 8 * 30 * 18;           // per-unit partial y values
static constexpr int SMEM_FLOATS = XS_ELEMS + PM_ELEMS + 32;
static constexpr int SMEM_BYTES  = SMEM_FLOATS * 4;    // ~43.8 KB

// wsum padded: [c][kd*5+kh][8] (5 kw + 3 ZERO pads -> {W4,0} 64-bit loads);
// [6400] = bias_sum
__device__ float g_wsum_pad[6404];

typedef unsigned long long ull;

#define FMA2(d, a, b) \
    asm("fma.rn.f32x2 %0, %1, %2, %0;" : "+l"(d) : "l"(a), "l"(b))

__device__ __forceinline__ ull bcast2(float x) {
    ull r;
    asm("mov.b64 %0, {%1, %1};" : "=l"(r) : "f"(x));
    return r;
}
__device__ __forceinline__ float2 unpack2(ull v) {
    float lo, hi;
    asm("mov.b64 {%0, %1}, %2;" : "=f"(lo), "=f"(hi) : "l"(v));
    return make_float2(lo, hi);
}

// ---------------------------------------------------------------------------
// Kernel 1: wsum[c][row][kw] = sum_o weight[c][o][kd,kh,kw] (pads = 0);
// bias_sum at [6400].  weight layout: (32,64,5,5,5) -> c*8000 + o*125 + k
// ---------------------------------------------------------------------------
__global__ void prep_kernel(const float* __restrict__ weight,
                            const float* __restrict__ bias) {
    int idx = blockIdx.x * blockDim.x + threadIdx.x;
    if (idx < 6400) {
        int c   = idx / 200;
        int rem = idx - c * 200;
        int row = rem >> 3;
        int col = rem & 7;
        float s = 0.f;
        if (col < 5) {
            const float* p = weight + c * 8000 + row * 5 + col;
            #pragma unroll 8
            for (int o = 0; o < 64; o++) s += p[o * 125];
        }
        g_wsum_pad[idx] = s;   // pads (col>=5) get 0
    } else if (idx == 6400) {
        float s = 0.f;
        #pragma unroll
        for (int o = 0; o < 64; o++) s += bias[o];
        g_wsum_pad[6400] = s;
    }
}

// ---------------------------------------------------------------------------
// Per-chunk compute for one work-unit: class (PA = od parity, PB = oh parity)
// restricted to kh-taps t in [T0, T0+NT).  Thread owns 3 a_off x 6 ow =
// 18 y-point PARTIALS as 9 f32x2 accumulators.
// Identity: od_l = 2*ld + kd - 4, kd = PA + 2s  =>  a_off = ld - 2 + s.
// ---------------------------------------------------------------------------
template <int PA, int PB, int T0, int NT>
__device__ __forceinline__ void compute_unit(const float* __restrict__ XS,
                                             const float* __restrict__ gw,
                                             int b_off, int w,
                                             ull (&acc)[9]) {
    constexpr int NS = 3 - PA;   // # kd taps
    const int xcol = 3 * w;

    for (int c = 0; c < CHUNK; c++) {
        const float* XC = XS + c * (25 * LWP);
        const float* WC = gw + c * 200;
        #pragma unroll
        for (int tt = 0; tt < NT; tt++) {
            const int t  = T0 + tt;
            const int lh = b_off + 2 - t;
            const int kh = PB + 2 * t;
            // Hoist the NS weight rows as packed 64-bit broadcasts.
            ull W01[NS], W23[NS], W40[NS];
            #pragma unroll
            for (int s = 0; s < NS; s++) {
                const ull* wr = reinterpret_cast<const ull*>(
                    WC + ((PA + 2 * s) * 5 + kh) * 8);
                W01[s] = __ldg(wr);
                W23[s] = __ldg(wr + 1);
                W40[s] = __ldg(wr + 2);   // {W4, 0} thanks to zero padding
            }
            #pragma unroll
            for (int ld = 0; ld < 5; ld++) {
                const int s_lo = (2 - ld) > 0 ? (2 - ld) : 0;
                const int s_hi_a = 4 - ld;
                const int s_hi = s_hi_a < (NS - 1) ? s_hi_a : (NS - 1);
                if (s_lo > s_hi) continue;   // folds at compile time

                const float* Xr = XC + (ld * 5 + lh) * LWP + xcol;
                const ull XX0 = bcast2(Xr[0]);
                const ull XX1 = bcast2(Xr[1]);
                const ull XX2 = bcast2(Xr[2]);
                const ull XX3 = bcast2(Xr[3]);
                const ull XX4 = bcast2(Xr[4]);
                #pragma unroll
                for (int s = 0; s < NS; s++) {
                    if (s < s_lo || s > s_hi) continue;
                    const int ao = ld - 2 + s;
                    ull* P = acc + ao * 3;
                    FMA2(P[0], XX2, W01[s]);
                    FMA2(P[0], XX1, W23[s]);
                    FMA2(P[0], XX0, W40[s]);
                    FMA2(P[1], XX3, W01[s]);
                    FMA2(P[1], XX2, W23[s]);
                    FMA2(P[1], XX1, W40[s]);
                    FMA2(P[2], XX4, W01[s]);
                    FMA2(P[2], XX3, W23[s]);
                    FMA2(P[2], XX2, W40[s]);
                }
            }
        }
    }
}

// Work-unit table (unit -> PA, PB, T0, NT); apps/channel in comments.
//  u0: class10 t{0,1} (12)   u1: class10 t{2}   (6)
//  u2: class11 t{0,1} (12)   u3: class00 t{0}   (9)
//  u4: class00 t{1}   (9)    u5: class00 t{2}   (9)
//  u6: class01 t{0}   (9)    u7: class01 t{1}   (9)
// SMSP pairs (u0,u1)=18 (u2,u3)=21 (u4,u5)=18 (u6,u7)=18; rotated per block.

// ---------------------------------------------------------------------------
// Kernel 2: fused transposed-conv (channel-summed) + 6x6x6/6 max pool.
// Block = (n, d, h); 256 threads = 8 work-unit warps; lanes 0..29 own
// (b_off, w); partial y summed across units in smem, then pooled.
// ---------------------------------------------------------------------------
__global__ __launch_bounds__(256, 4)
void fused_kernel(const float* __restrict__ x, float* __restrict__ out) {
    extern __shared__ float smem[];
    float* XS  = smem;                          // [8][5][5][LWP]
    float* PM  = smem + XS_ELEMS;               // [8 units][30 cells][18]
    float* PMM = PM + PM_ELEMS;                 // [30] cell maxima

    const int h = blockIdx.x;
    const int d = blockIdx.y;
    const int n = blockIdx.z;
    const int tid   = threadIdx.x;
    const int wid   = tid >> 5;
    const int lane  = tid & 31;
    const int b_off = lane / 10;       // 0..2 (lanes 30,31 compute garbage, never stored)
    const int w     = lane - b_off * 10;

    // Rotate unit-pairs across SMSPs by block index to average SMSP load.
    const int rot  = blockIdx.x + blockIdx.y + blockIdx.z;
    const int pair = ((wid & 3) + rot) & 3;
    const int unit = pair * 2 + (wid >> 2);

    const int id0 = 3 * d - 1;
    const int ih0 = 3 * h - 1;
    const float* xn = x + (long)n * (CIN * DIN * HIN * WIN);

    // --- precompute staging row tables (div/mod done once) ---
    const int rowid = wid;             // rows r = rowid + 8*rr, rr<4
    bool rok[4], vld[4];
    int  goff[4], doff[4];
    #pragma unroll
    for (int rr = 0; rr < 4; rr++) {
        int r  = rowid + 8 * rr;
        rok[rr] = (r < 25);
        int rc = r < 25 ? r : 24;
        int ld = rc / 5;
        int lh = rc - ld * 5;
        int id = id0 + ld;
        int ih = ih0 + lh;
        vld[rr]  = (id >= 0) && (ih >= 0);   // upper bounds always in range
        goff[rr] = id * (HIN * WIN) + ih * WIN + lane;
        doff[rr] = rc * LWP + 1 + lane;      // lw = iw + 1
    }

    ull acc[9];
    #pragma unroll
    for (int i = 0; i < 9; i++) acc[i] = 0ull;

    for (int chunk = 0; chunk < 4; chunk++) {
        if (chunk) __syncthreads();          // protect XS before re-staging
        // ---- stage x chunk (8 channels): lanes map 1:1 to iw, coalesced ----
        const float* xc = xn + chunk * (CHUNK * DIN * HIN * WIN);
        for (int c = 0; c < CHUNK; c++) {
            const int bg = c * (DIN * HIN * WIN);
            const int bd = c * (25 * LWP);
            #pragma unroll
            for (int rr = 0; rr < 4; rr++) {
                if (rok[rr]) {
                    float v = vld[rr] ? __ldg(xc + bg + goff[rr]) : 0.f;
                    XS[bd + doff[rr]] = v;
                    if (lane == 0) XS[bd + doff[rr] - 1] = 0.f;  // lw=0 pad col
                }
            }
        }
        __syncthreads();

        const float* gw = g_wsum_pad + chunk * (CHUNK * 200);
        switch (unit) {
            case 0: compute_unit<1, 0, 0, 2>(XS, gw, b_off, w, acc); break;
            case 1: compute_unit<1, 0, 2, 1>(XS, gw, b_off, w, acc); break;
            case 2: compute_unit<1, 1, 0, 2>(XS, gw, b_off, w, acc); break;
            case 3: compute_unit<0, 0, 0, 1>(XS, gw, b_off, w, acc); break;
            case 4: compute_unit<0, 0, 1, 1>(XS, gw, b_off, w, acc); break;
            case 5: compute_unit<0, 0, 2, 1>(XS, gw, b_off, w, acc); break;
            case 6: compute_unit<0, 1, 0, 1>(XS, gw, b_off, w, acc); break;
            default: compute_unit<0, 1, 1, 1>(XS, gw, b_off, w, acc); break;
        }
    }
    __syncthreads();

    // ---- store this unit's 18 y-partials for its (b_off, w) cell ----
    if (lane < 30) {
        float* P = PM + (unit * 30 + lane) * 18;
        #pragma unroll
        for (int i = 0; i < 9; i++) {
            float2 v = unpack2(acc[i]);
            P[2 * i]     = v.x;
            P[2 * i + 1] = v.y;
        }
    }
    __syncthreads();

    // ---- per-cell: sum unit partials per class, max over 72 y-points ----
    if (tid < 30) {
        const float* B = PM + tid * 18;
        float m = -CUDART_INF_F;
        #pragma unroll
        for (int i = 0; i < 18; i++) {
            // class10 = u0 + u1, class11 = u2, class00 = u3+u4+u5, class01 = u6+u7
            float y10 = B[0 * 540 + i] + B[1 * 540 + i];
            float y11 = B[2 * 540 + i];
            float y00 = B[3 * 540 + i] + B[4 * 540 + i] + B[5 * 540 + i];
            float y01 = B[6 * 540 + i] + B[7 * 540 + i];
            m = fmaxf(m, fmaxf(fmaxf(y10, y11), fmaxf(y00, y01)));
        }
        PMM[tid] = m;
    }
    __syncthreads();

    // ---- final: max over b_off, add bias_sum, emit ----
    if (tid < OWp) {
        float mm = fmaxf(fmaxf(PMM[tid], PMM[10 + tid]), PMM[20 + tid]);
        const float bs = g_wsum_pad[6400];
        out[(((long)n * ODp + d) * OHp + h) * OWp + tid] = mm + bs;
    }
}

// ---------------------------------------------------------------------------
extern "C" void kernel_launch(void* const* d_in, const int* in_sizes, int n_in,
                              void* d_out, int out_size) {
    (void)in_sizes; (void)n_in; (void)out_size;
    const float* x      = (const float*)d_in[0];
    const float* weight = (const float*)d_in[1];
    const float* bias   = (const float*)d_in[2];
    float* out = (float*)d_out;

    prep_kernel<<<26, 256>>>(weight, bias);
    fused_kernel<<<dim3(OHp, ODp, NB), 256, SMEM_BYTES>>>(x, out);
}

// round 10
// speedup vs baseline: 1.0423x; 1.0423x over previous
#include <cuda_runtime.h>
#include <math_constants.h>

// Problem constants (from reference setup_inputs)
static constexpr int NB  = 16;   // batch
static constexpr int CIN = 32;   // input channels
static constexpr int DIN = 16;
static constexpr int HIN = 32;
static constexpr int WIN = 32;
static constexpr int ODp = 5;    // pooled output dims
static constexpr int OHp = 10;
static constexpr int OWp = 10;

// 4 chunks of 8 channels staged; each warp-group computes 4 of the 8.
static constexpr int CHUNK = 8;
static constexpr int CPG   = 4;                        // channels per group
static constexpr int LWP   = 33;                       // padded x row (conflict-free)
static constexpr int XS_ELEMS  = CHUNK * 5 * 5 * LWP;  // 6600
static constexpr int PM2_ELEMS = 2 * 4 * 30 * 18;      // [group][class][cell][pt]
static constexpr int PMM_ELEMS = 120;
static constexpr int SMEM_BYTES = (XS_ELEMS + PM2_ELEMS + PMM_ELEMS + 8) * 4; // ~44.3KB

// wsum padded: [c][kd*5+kh][8] (5 kw + 3 ZERO pads -> {W4,0} 64-bit loads);
// [6400] = bias_sum
__device__ float g_wsum_pad[6404];

typedef unsigned long long ull;

#define FMA2(d, a, b) \
    asm("fma.rn.f32x2 %0, %1, %2, %0;" : "+l"(d) : "l"(a), "l"(b))

__device__ __forceinline__ ull bcast2(float x) {
    ull r;
    asm("mov.b64 %0, {%1, %1};" : "=l"(r) : "f"(x));
    return r;
}
__device__ __forceinline__ float2 unpack2(ull v) {
    float lo, hi;
    asm("mov.b64 {%0, %1}, %2;" : "=f"(lo), "=f"(hi) : "l"(v));
    return make_float2(lo, hi);
}

// ---------------------------------------------------------------------------
// Kernel 1: wsum[c][row][kw] = sum_o weight[c][o][kd,kh,kw] (pads = 0);
// bias_sum at [6400].  weight layout: (32,64,5,5,5) -> c*8000 + o*125 + k
// ---------------------------------------------------------------------------
__global__ void prep_kernel(const float* __restrict__ weight,
                            const float* __restrict__ bias) {
    int idx = blockIdx.x * blockDim.x + threadIdx.x;
    if (idx < 6400) {
        int c   = idx / 200;
        int rem = idx - c * 200;
        int row = rem >> 3;
        int col = rem & 7;
        float s = 0.f;
        if (col < 5) {
            const float* p = weight + c * 8000 + row * 5 + col;
            #pragma unroll 8
            for (int o = 0; o < 64; o++) s += p[o * 125];
        }
        g_wsum_pad[idx] = s;   // pads (col>=5) get 0
    } else if (idx == 6400) {
        float s = 0.f;
        #pragma unroll
        for (int o = 0; o < 64; o++) s += bias[o];
        g_wsum_pad[6400] = s;
    }
}

// ---------------------------------------------------------------------------
// Per-chunk compute for class (PA = od parity, PB = oh parity), channels
// [C0, C0+CPG). Thread owns 3 a_off x 6 ow = 18 y-point channel-PARTIALS as
// 9 f32x2 accumulators.  Identity: a_off = ld - 2 + s, kd = PA + 2s.
// Weights read as warp-uniform 64-bit __ldg broadcasts from g_wsum_pad.
// ---------------------------------------------------------------------------
template <int PA, int PB>
__device__ __forceinline__ void compute_chunk(const float* __restrict__ XS,
                                              const float* __restrict__ gw,
                                              int C0, int b_off, int w,
                                              ull (&acc)[9]) {
    constexpr int NS = 3 - PA;   // # kd taps
    constexpr int NT = 3 - PB;   // # kh taps
    const int xcol = 3 * w;

    for (int c = C0; c < C0 + CPG; c++) {
        const float* XC = XS + c * (25 * LWP);
        const float* WC = gw + c * 200;
        #pragma unroll
        for (int t = 0; t < NT; t++) {
            const int lh = b_off + 2 - t;
            const int kh = PB + 2 * t;
            // Hoist the NS weight rows as packed 64-bit broadcasts.
            ull W01[NS], W23[NS], W40[NS];
            #pragma unroll
            for (int s = 0; s < NS; s++) {
                const ull* wr = reinterpret_cast<const ull*>(
                    WC + ((PA + 2 * s) * 5 + kh) * 8);
                W01[s] = __ldg(wr);
                W23[s] = __ldg(wr + 1);
                W40[s] = __ldg(wr + 2);   // {W4, 0} thanks to zero padding
            }
            #pragma unroll
            for (int ld = 0; ld < 5; ld++) {
                const int s_lo = (2 - ld) > 0 ? (2 - ld) : 0;
                const int s_hi_a = 4 - ld;
                const int s_hi = s_hi_a < (NS - 1) ? s_hi_a : (NS - 1);
                if (s_lo > s_hi) continue;   // folds at compile time

                const float* Xr = XC + (ld * 5 + lh) * LWP + xcol;
                const ull XX0 = bcast2(Xr[0]);
                const ull XX1 = bcast2(Xr[1]);
                const ull XX2 = bcast2(Xr[2]);
                const ull XX3 = bcast2(Xr[3]);
                const ull XX4 = bcast2(Xr[4]);
                #pragma unroll
                for (int s = 0; s < NS; s++) {
                    if (s < s_lo || s > s_hi) continue;
                    const int ao = ld - 2 + s;
                    ull* P = acc + ao * 3;
                    FMA2(P[0], XX2, W01[s]);
                    FMA2(P[0], XX1, W23[s]);
                    FMA2(P[0], XX0, W40[s]);
                    FMA2(P[1], XX3, W01[s]);
                    FMA2(P[1], XX2, W23[s]);
                    FMA2(P[1], XX1, W40[s]);
                    FMA2(P[2], XX4, W01[s]);
                    FMA2(P[2], XX3, W23[s]);
                    FMA2(P[2], XX2, W40[s]);
                }
            }
        }
    }
}

// ---------------------------------------------------------------------------
// Kernel 2: fused transposed-conv (channel-summed) + 6x6x6/6 max pool.
// Block = (n, d, h); 256 threads = 2 channel-groups x 4 class-warps.
// Group 1 reverses class order so each SMSP hosts classes (i, 3-i):
// per-SMSP FMA2 spread 1.08 (vs 2.25 unbalanced).
// ---------------------------------------------------------------------------
__global__ __launch_bounds__(256, 4)
void fused_kernel(const float* __restrict__ x, float* __restrict__ out) {
    extern __shared__ float smem[];
    float* XS  = smem;                          // [8][5][5][LWP]
    float* PM2 = smem + XS_ELEMS;               // [2][4][30][18]
    float* PMM = PM2 + PM2_ELEMS;               // [4][30]

    const int h = blockIdx.x;
    const int d = blockIdx.y;
    const int n = blockIdx.z;
    const int tid   = threadIdx.x;
    const int wid   = tid >> 5;
    const int lane  = tid & 31;
    const int group = wid >> 2;            // 0 or 1 (channel half)
    const int clsR  = wid & 3;
    const int cls   = group ? (3 - clsR) : clsR;   // SMSP-balanced class
    const int C0    = group * CPG;
    const int b_off = lane / 10;           // 0..2 (lanes 30,31: garbage, unstored)
    const int w     = lane - b_off * 10;

    const int id0 = 3 * d - 1;
    const int ih0 = 3 * h - 1;
    const float* xn = x + (long)n * (CIN * DIN * HIN * WIN);

    // --- precompute staging row tables: rows r = wid + 8*rr, rr < 4 ---
    bool rok[4], vld[4];
    int  goff[4], doff[4];
    #pragma unroll
    for (int rr = 0; rr < 4; rr++) {
        int r  = wid + 8 * rr;
        rok[rr] = (r < 25);
        int rc = r < 25 ? r : 24;
        int ld = rc / 5;
        int lh = rc - ld * 5;
        int id = id0 + ld;
        int ih = ih0 + lh;
        vld[rr]  = (id >= 0) && (ih >= 0);   // upper bounds always in range
        goff[rr] = id * (HIN * WIN) + ih * WIN + lane;
        doff[rr] = rc * LWP + 1 + lane;      // lw = iw + 1
    }

    ull acc[9];
    #pragma unroll
    for (int i = 0; i < 9; i++) acc[i] = 0ull;

    for (int chunk = 0; chunk < 4; chunk++) {
        if (chunk) __syncthreads();          // protect XS before re-staging
        // ---- stage x chunk (8 channels): lanes map 1:1 to iw, coalesced ----
        const float* xc = xn + chunk * (CHUNK * DIN * HIN * WIN);
        for (int c = 0; c < CHUNK; c++) {
            const int bg = c * (DIN * HIN * WIN);
            const int bd = c * (25 * LWP);
            #pragma unroll
            for (int rr = 0; rr < 4; rr++) {
                if (rok[rr]) {
                    float v = vld[rr] ? __ldg(xc + bg + goff[rr]) : 0.f;
                    XS[bd + doff[rr]] = v;
                    if (lane == 0) XS[bd + doff[rr] - 1] = 0.f;  // lw=0 pad col
                }
            }
        }
        __syncthreads();

        const float* gw = g_wsum_pad + chunk * (CHUNK * 200);
        if      (cls == 0) compute_chunk<0, 0>(XS, gw, C0, b_off, w, acc);
        else if (cls == 1) compute_chunk<0, 1>(XS, gw, C0, b_off, w, acc);
        else if (cls == 2) compute_chunk<1, 0>(XS, gw, C0, b_off, w, acc);
        else               compute_chunk<1, 1>(XS, gw, C0, b_off, w, acc);
    }
    __syncthreads();

    // ---- store this (group, class) 18 channel-partials for the cell ----
    if (lane < 30) {
        float* P = PM2 + ((group * 4 + cls) * 30 + lane) * 18;
        #pragma unroll
        for (int i = 0; i < 9; i++) {
            float2 v = unpack2(acc[i]);
            P[2 * i]     = v.x;
            P[2 * i + 1] = v.y;
        }
    }
    __syncthreads();

    // ---- per (class, cell): sum the two channel-groups, max over 18 pts ----
    if (tid < 120) {
        const int c2   = tid / 30;
        const int cell = tid - c2 * 30;
        const float* A = PM2 + (c2 * 30 + cell) * 18;          // group 0
        const float* B = A + 4 * 30 * 18;                       // group 1
        float m = -CUDART_INF_F;
        #pragma unroll
        for (int i = 0; i < 18; i++) m = fmaxf(m, A[i] + B[i]);
        PMM[tid] = m;
    }
    __syncthreads();

    // ---- final: max over classes and b_off, add bias_sum, emit ----
    if (tid < OWp) {
        float mm = -CUDART_INF_F;
        #pragma unroll
        for (int c2 = 0; c2 < 4; c2++)
            #pragma unroll
            for (int bo = 0; bo < 3; bo++)
                mm = fmaxf(mm, PMM[c2 * 30 + bo * 10 + tid]);
        const float bs = g_wsum_pad[6400];
        out[(((long)n * ODp + d) * OHp + h) * OWp + tid] = mm + bs;
    }
}

// ---------------------------------------------------------------------------
extern "C" void kernel_launch(void* const* d_in, const int* in_sizes, int n_in,
                              void* d_out, int out_size) {
    (void)in_sizes; (void)n_in; (void)out_size;
    const float* x      = (const float*)d_in[0];
    const float* weight = (const float*)d_in[1];
    const float* bias   = (const float*)d_in[2];
    float* out = (float*)d_out;

    prep_kernel<<<26, 256>>>(weight, bias);
    fused_kernel<<<dim3(OHp, ODp, NB), 256, SMEM_BYTES>>>(x, out);
}

// round 11
// speedup vs baseline: 1.2504x; 1.1996x over previous
#include <cuda_runtime.h>
#include <math_constants.h>

// Problem constants (from reference setup_inputs)
static constexpr int NB  = 16;   // batch
static constexpr int CIN = 32;   // input channels
static constexpr int DIN = 16;
static constexpr int HIN = 32;
static constexpr int WIN = 32;
static constexpr int ODp = 5;    // pooled output dims
static constexpr int OHp = 10;
static constexpr int OWp = 10;

// 4 chunks of 8 channels staged; each warp computes 4 of the 8 (its half).
static constexpr int CHUNK = 8;
static constexpr int CPG   = 4;                        // channels per group
static constexpr int LWP   = 33;                       // padded x row (conflict-free)
static constexpr int XS_ELEMS  = CHUNK * 5 * 5 * LWP;  // 6600
static constexpr int PM2_ELEMS = 2 * 2 * 30 * 36;      // [pb][group][cell][pt] = 4320
static constexpr int PMM_ELEMS = 60;
static constexpr int SMEM_BYTES = (XS_ELEMS + PM2_ELEMS + PMM_ELEMS) * 4; // 43,920 B

// wsum padded: [c][kd*5+kh][8] (5 kw + 3 ZERO pads -> {W4,0} 64-bit loads);
// [6400] = bias_sum
__device__ float g_wsum_pad[6404];

typedef unsigned long long ull;

#define FMA2(d, a, b) \
    asm("fma.rn.f32x2 %0, %1, %2, %0;" : "+l"(d) : "l"(a), "l"(b))

__device__ __forceinline__ ull bcast2(float x) {
    ull r;
    asm("mov.b64 %0, {%1, %1};" : "=l"(r) : "f"(x));
    return r;
}
__device__ __forceinline__ float2 unpack2(ull v) {
    float lo, hi;
    asm("mov.b64 {%0, %1}, %2;" : "=f"(lo), "=f"(hi) : "l"(v));
    return make_float2(lo, hi);
}

// ---------------------------------------------------------------------------
// Kernel 1: wsum[c][row][kw] = sum_o weight[c][o][kd,kh,kw] (pads = 0);
// bias_sum at [6400].  weight layout: (32,64,5,5,5) -> c*8000 + o*125 + k
// ---------------------------------------------------------------------------
__global__ void prep_kernel(const float* __restrict__ weight,
                            const float* __restrict__ bias) {
    int idx = blockIdx.x * blockDim.x + threadIdx.x;
    if (idx < 6400) {
        int c   = idx / 200;
        int rem = idx - c * 200;
        int row = rem >> 3;
        int col = rem & 7;
        float s = 0.f;
        if (col < 5) {
            const float* p = weight + c * 8000 + row * 5 + col;
            #pragma unroll 8
            for (int o = 0; o < 64; o++) s += p[o * 125];
        }
        g_wsum_pad[idx] = s;   // pads (col>=5) get 0
    } else if (idx == 6400) {
        float s = 0.f;
        #pragma unroll
        for (int o = 0; o < 64; o++) s += bias[o];
        g_wsum_pad[6400] = s;
    }
}

// ---------------------------------------------------------------------------
// Per-chunk compute for oh-parity PB, channels [C0, C0+CPG).
// Thread owns oh_l = 2*b_off + PB fixed, ALL 6 od_l, 6 ow -> 36 y partials
// as 18 f32x2 accumulators acc[od_l*3 + owpair].
// Identity: od_l = 2*ld + kd - 4 (valid when 0 <= od_l <= 5);
//           oh tap t: lh = b_off + 2 - t, kh = PB + 2t.
// Each X row is loaded once (5 LDS) and applied to all valid kd taps
// (up to 5 weight rows -> up to 45 FMA2 per row load).
// ---------------------------------------------------------------------------
template <int PB>
__device__ __forceinline__ void compute_chunk(const float* __restrict__ XS,
                                              const float* __restrict__ gw,
                                              int C0, int b_off, int w,
                                              ull (&acc)[18]) {
    constexpr int NT = 3 - PB;   // # kh taps
    const int xcol = 3 * w;

    for (int c = C0; c < C0 + CPG; c++) {
        const float* XC = XS + c * (25 * LWP);
        const float* WC = gw + c * 200;
        #pragma unroll
        for (int t = 0; t < NT; t++) {
            const int lh = b_off + 2 - t;
            const int kh = PB + 2 * t;
            // Hoist all 5 kd weight rows for this kh (uniform 64-bit LDG).
            ull W01[5], W23[5], W40[5];
            #pragma unroll
            for (int kd = 0; kd < 5; kd++) {
                const ull* wr = reinterpret_cast<const ull*>(
                    WC + (kd * 5 + kh) * 8);
                W01[kd] = __ldg(wr);
                W23[kd] = __ldg(wr + 1);
                W40[kd] = __ldg(wr + 2);   // {W4, 0} thanks to zero padding
            }
            #pragma unroll
            for (int ld = 0; ld < 5; ld++) {
                const float* Xr = XC + (ld * 5 + lh) * LWP + xcol;
                const ull XX0 = bcast2(Xr[0]);
                const ull XX1 = bcast2(Xr[1]);
                const ull XX2 = bcast2(Xr[2]);
                const ull XX3 = bcast2(Xr[3]);
                const ull XX4 = bcast2(Xr[4]);
                #pragma unroll
                for (int kd = 0; kd < 5; kd++) {
                    const int od = 2 * ld + kd - 4;
                    if (od < 0 || od > 5) continue;   // folds at compile time
                    ull* P = acc + od * 3;
                    FMA2(P[0], XX2, W01[kd]);
                    FMA2(P[0], XX1, W23[kd]);
                    FMA2(P[0], XX0, W40[kd]);
                    FMA2(P[1], XX3, W01[kd]);
                    FMA2(P[1], XX2, W23[kd]);
                    FMA2(P[1], XX1, W40[kd]);
                    FMA2(P[2], XX4, W01[kd]);
                    FMA2(P[2], XX3, W23[kd]);
                    FMA2(P[2], XX2, W40[kd]);
                }
            }
        }
    }
}

// ---------------------------------------------------------------------------
// Kernel 2: fused transposed-conv (channel-summed) + 6x6x6/6 max pool.
// Block = (n, d, h); 128 threads = 4 warps = (pb, channel-half); pb mapping
// swapped by block parity so SMSPs average the pb0/pb1 load across CTAs.
// Lanes 0..29 own (b_off, w); each thread computes 36 y-partials.
// ---------------------------------------------------------------------------
__global__ __launch_bounds__(128, 5)
void fused_kernel(const float* __restrict__ x, float* __restrict__ out) {
    extern __shared__ float smem[];
    float* XS  = smem;                          // [8][5][5][LWP]
    float* PM2 = smem + XS_ELEMS;               // [2 pb][2 group][30][36]
    float* PMM = PM2 + PM2_ELEMS;               // [2 pb][30]

    const int h = blockIdx.x;
    const int d = blockIdx.y;
    const int n = blockIdx.z;
    const int tid   = threadIdx.x;
    const int wid   = tid >> 5;
    const int lane  = tid & 31;
    const int par   = (blockIdx.x + blockIdx.y + blockIdx.z) & 1;
    const int pb    = (wid >> 1) ^ par;    // oh parity (block-parity swapped)
    const int group = wid & 1;             // channel half
    const int C0    = group * CPG;
    const int b_off = lane / 10;           // 0..2 (lanes 30,31: garbage, unstored)
    const int w     = lane - b_off * 10;

    const int id0 = 3 * d - 1;
    const int ih0 = 3 * h - 1;
    const float* xn = x + (long)n * (CIN * DIN * HIN * WIN);

    // --- precompute staging row tables: rows r = wid + 4*rr, rr < 7 ---
    bool rok[7], vld[7];
    int  goff[7], doff[7];
    #pragma unroll
    for (int rr = 0; rr < 7; rr++) {
        int r  = wid + 4 * rr;
        rok[rr] = (r < 25);
        int rc = r < 25 ? r : 24;
        int ld = rc / 5;
        int lh = rc - ld * 5;
        int id = id0 + ld;
        int ih = ih0 + lh;
        vld[rr]  = (id >= 0) && (ih >= 0);   // upper bounds always in range
        goff[rr] = id * (HIN * WIN) + ih * WIN + lane;
        doff[rr] = rc * LWP + 1 + lane;      // lw = iw + 1
    }

    ull acc[18];
    #pragma unroll
    for (int i = 0; i < 18; i++) acc[i] = 0ull;

    for (int chunk = 0; chunk < 4; chunk++) {
        if (chunk) __syncthreads();          // protect XS before re-staging
        // ---- stage x chunk (8 channels): lanes map 1:1 to iw, coalesced ----
        const float* xc = xn + chunk * (CHUNK * DIN * HIN * WIN);
        for (int c = 0; c < CHUNK; c++) {
            const int bg = c * (DIN * HIN * WIN);
            const int bd = c * (25 * LWP);
            #pragma unroll
            for (int rr = 0; rr < 7; rr++) {
                if (rok[rr]) {
                    float v = vld[rr] ? __ldg(xc + bg + goff[rr]) : 0.f;
                    XS[bd + doff[rr]] = v;
                    if (lane == 0) XS[bd + doff[rr] - 1] = 0.f;  // lw=0 pad col
                }
            }
        }
        __syncthreads();

        const float* gw = g_wsum_pad + chunk * (CHUNK * 200);
        if (pb == 0) compute_chunk<0>(XS, gw, C0, b_off, w, acc);
        else         compute_chunk<1>(XS, gw, C0, b_off, w, acc);
    }
    __syncthreads();

    // ---- store this (pb, group) 36 channel-partials for the cell ----
    if (lane < 30) {
        float* P = PM2 + ((pb * 2 + group) * 30 + lane) * 36;
        #pragma unroll
        for (int i = 0; i < 18; i++) {
            float2 v = unpack2(acc[i]);
            P[2 * i]     = v.x;
            P[2 * i + 1] = v.y;
        }
    }
    __syncthreads();

    // ---- per (pb, cell): sum the two channel-groups, max over 36 pts ----
    if (tid < 60) {
        const int p2   = tid / 30;
        const int cell = tid - p2 * 30;
        const float* A = PM2 + (p2 * 2 * 30 + cell) * 36;   // group 0
        const float* B = A + 30 * 36;                        // group 1
        float m = -CUDART_INF_F;
        #pragma unroll
        for (int i = 0; i < 36; i++) m = fmaxf(m, A[i] + B[i]);
        PMM[p2 * 30 + cell] = m;
    }
    __syncthreads();

    // ---- final: max over pb and b_off, add bias_sum, emit ----
    if (tid < OWp) {
        float mm = -CUDART_INF_F;
        #pragma unroll
        for (int p2 = 0; p2 < 2; p2++)
            #pragma unroll
            for (int bo = 0; bo < 3; bo++)
                mm = fmaxf(mm, PMM[p2 * 30 + bo * 10 + tid]);
        const float bs = g_wsum_pad[6400];
        out[(((long)n * ODp + d) * OHp + h) * OWp + tid] = mm + bs;
    }
}

// ---------------------------------------------------------------------------
extern "C" void kernel_launch(void* const* d_in, const int* in_sizes, int n_in,
                              void* d_out, int out_size) {
    (void)in_sizes; (void)n_in; (void)out_size;
    const float* x      = (const float*)d_in[0];
    const float* weight = (const float*)d_in[1];
    const float* bias   = (const float*)d_in[2];
    float* out = (float*)d_out;

    prep_kernel<<<26, 256>>>(weight, bias);
    fused_kernel<<<dim3(OHp, ODp, NB), 128, SMEM_BYTES>>>(x, out);
}